// round 6
// baseline (speedup 1.0000x reference)
#include <cuda_runtime.h>

#define NN 4096
#define DIM 64
#define INF_V 1e10f
#define NBLK 64           // 64 rows per band: one warp, 2 rows/lane, 4 cols/tile
#define NTILE 1024        // tile-columns (4 cols each)

// Scratch (static __device__ arrays: allocation-free per harness rules)
__device__ float g_D[(size_t)NN * NN];    // 64 MB cost matrix
__device__ float g_xn[NN];
__device__ float g_yn[NN];
__device__ float g_bnd[NBLK][NN + 32];    // bottom boundary row (+pad for prefetch overrun)
__device__ int   g_prog[NBLK];            // tiles published per block

// ---------------- norms ----------------
__global__ void norms_kernel(const float* __restrict__ x, const float* __restrict__ y) {
    int w = (blockIdx.x * blockDim.x + threadIdx.x) >> 5;
    int lane = threadIdx.x & 31;
    if (w >= 2 * NN) return;
    const float* src = (w < NN) ? x : y;
    int row = (w < NN) ? w : w - NN;
    float a = src[row * DIM + lane];
    float b = src[row * DIM + 32 + lane];
    float s = a * a + b * b;
    #pragma unroll
    for (int o = 16; o; o >>= 1) s += __shfl_xor_sync(0xffffffffu, s, o);
    if (lane == 0) { if (w < NN) g_xn[row] = s; else g_yn[row] = s; }
}

// ---------------- D = |x|^2 + |y|^2 - 2 x.y  (64x64 tile per block) ----------------
__global__ void dmat_kernel(const float* __restrict__ x, const float* __restrict__ y) {
    __shared__ float xs[64][65];
    __shared__ float ys[64][65];
    int tx = threadIdx.x, ty = threadIdx.y;
    int tid = ty * 16 + tx;
    int rb = blockIdx.y * 64, cb = blockIdx.x * 64;

    for (int i = tid; i < 64 * 64; i += 256) {
        int rr = i >> 6, kk = i & 63;
        xs[rr][kk] = x[(rb + rr) * DIM + kk];
        ys[rr][kk] = y[(cb + rr) * DIM + kk];
    }
    __syncthreads();

    float acc[4][4] = {};
    #pragma unroll
    for (int k = 0; k < 64; k++) {
        float xv[4], yv[4];
        #pragma unroll
        for (int i = 0; i < 4; i++) xv[i] = xs[ty + 16 * i][k];
        #pragma unroll
        for (int j = 0; j < 4; j++) yv[j] = ys[tx + 16 * j][k];
        #pragma unroll
        for (int i = 0; i < 4; i++)
            #pragma unroll
            for (int j = 0; j < 4; j++)
                acc[i][j] += xv[i] * yv[j];
    }

    #pragma unroll
    for (int i = 0; i < 4; i++) {
        int r = rb + ty + 16 * i;
        float xnr = g_xn[r];
        #pragma unroll
        for (int j = 0; j < 4; j++) {
            int c = cb + tx + 16 * j;
            g_D[(size_t)r * NN + c] = xnr + g_yn[c] - 2.0f * acc[i][j];
        }
    }
}

// ---------------- reset progress flags ----------------
__global__ void init_kernel() {
    if (threadIdx.x < NBLK) g_prog[threadIdx.x] = 0;
}

// ---------------- DP wavefront: 2x4 register tiles, 64 warps ----------------
__device__ __forceinline__ int ld_acq(const int* p) {
    int v;
    asm volatile("ld.acquire.gpu.u32 %0, [%1];" : "=r"(v) : "l"(p) : "memory");
    return v;
}
__device__ __forceinline__ void st_rel(int* p, int v) {
    asm volatile("st.release.gpu.u32 [%0], %1;" :: "l"(p), "r"(v) : "memory");
}

#define CELL(nv, u, d, l, cost) do {                                   \
    float m_ = fminf(fminf((u), (d)), (l));                            \
    float s_ = __expf(m_ - (u)) + __expf(m_ - (d)) + __expf(m_ - (l)); \
    (nv) = (cost) + m_ - __logf(s_);                                   \
} while (0)

__global__ void __launch_bounds__(32, 1) dp_kernel(float* __restrict__ out) {
    __shared__ float topb[2][18];   // double-buffered boundary windows

    const int b = blockIdx.x;
    const int L = threadIdx.x;
    const int row0 = b * 64 + 2 * L;
    const float4* __restrict__ Dr0 = (const float4*)(g_D + (size_t)(row0 + 0) * NN);
    const float4* __restrict__ Dr1 = (const float4*)(g_D + (size_t)(row0 + 1) * NN);
    float* mybnd = g_bnd[b];
    const float* upbnd = (b > 0) ? g_bnd[b - 1] : (const float*)0;

    float lft0 = INF_V, lft1 = INF_V;   // v[row0][4j-1], v[row1][4j-1]
    float bot0 = INF_V, bot1 = INF_V, bot2 = INF_V, bot3 = INF_V;
    float dgv = INF_V;                  // v[row0-1][4j-1]

    // ---- prologue: stage group-0 window (cols -1..15) ----
    if (b == 0) {
        if (L < 18) { topb[0][L] = INF_V; topb[1][L] = INF_V; }
    } else if (L < 17) {
        while (ld_acq(&g_prog[b - 1]) < 4) { }
        int col = L - 1;
        topb[0][L] = (col >= 0) ? __ldcg(&upbnd[col]) : INF_V;
    }
    __syncwarp();

    float4 c0 = __ldg(Dr0), c1 = __ldg(Dr1);   // tile-0 costs

    const int TT = NTILE + 31;
    #pragma unroll 1
    for (int tau = 0; tau < TT; tau++) {
        const int j = tau - L;

        // ---- stage NEXT group's boundary window (off the consume path) ----
        if (b > 0 && tau < NTILE && (tau & 3) == 0) {
            int g = tau >> 2;
            __syncwarp();                       // last group's window writes visible
            if (L < 17) {
                int need = 4 * g + 8; if (need > NTILE) need = NTILE;
                while (ld_acq(&g_prog[b - 1]) < need) { }
                topb[(g + 1) & 1][L] = __ldcg(&upbnd[16 * g + 15 + L]);
            }
        }

        // ---- prefetch next tile costs ----
        int jn = j + 1; if (jn < 0) jn = 0; if (jn > NTILE - 1) jn = NTILE - 1;
        float4 p0 = __ldg(Dr0 + jn);
        float4 p1 = __ldg(Dr1 + jn);

        // ---- top handoff: neighbor's bottom row from previous step ----
        float t0 = __shfl_up_sync(0xffffffffu, bot0, 1);
        float t1 = __shfl_up_sync(0xffffffffu, bot1, 1);
        float t2 = __shfl_up_sync(0xffffffffu, bot2, 1);
        float t3 = __shfl_up_sync(0xffffffffu, bot3, 1);
        if (L == 0) {
            if (b == 0) {
                t0 = t1 = t2 = t3 = INF_V;
                dgv = (tau == 0) ? 0.0f : INF_V;
            } else {
                const float* w = topb[(tau >> 2) & 1];
                int p = (tau & 3) * 4;
                dgv = w[p];
                t0 = w[p + 1]; t1 = w[p + 2]; t2 = w[p + 3]; t3 = w[p + 4];
            }
        }

        if (j >= 0 && j < NTILE) {
            float u0 = t0, u1 = t1, u2 = t2, u3 = t3;
            float n0, n1, n2, n3, newl0;
            {   // row 0
                float d = dgv, l = lft0;
                CELL(n0, u0, d, l, c0.x); d = u0; l = n0;
                CELL(n1, u1, d, l, c0.y); d = u1; l = n1;
                CELL(n2, u2, d, l, c0.z); d = u2; l = n2;
                CELL(n3, u3, d, l, c0.w);
                newl0 = n3;
                u0 = n0; u1 = n1; u2 = n2; u3 = n3;
            }
            {   // row 1 (diag at k=0 is OLD lft0)
                float d = lft0, l = lft1;
                CELL(n0, u0, d, l, c1.x); d = u0; l = n0;
                CELL(n1, u1, d, l, c1.y); d = u1; l = n1;
                CELL(n2, u2, d, l, c1.z); d = u2; l = n2;
                CELL(n3, u3, d, l, c1.w);
                u0 = n0; u1 = n1; u2 = n2; u3 = n3;
            }
            lft0 = newl0; lft1 = u3;
            bot0 = u0; bot1 = u1; bot2 = u2; bot3 = u3;

            if (L == 31) {
                *(float4*)&mybnd[4 * j] = make_float4(bot0, bot1, bot2, bot3);
                if ((j & 3) == 3 && b < NBLK - 1)
                    st_rel(&g_prog[b], j + 1);   // release orders mybnd stores
            }
        }
        dgv = t3;                                // diag for next tile = top row last col
        c0 = p0; c1 = p1;
    }

    if (b == NBLK - 1 && L == 31) out[0] = lft1; // dp[4096][4096]
}

extern "C" void kernel_launch(void* const* d_in, const int* in_sizes, int n_in,
                              void* d_out, int out_size) {
    const float* x = (const float*)d_in[0];
    const float* y = (const float*)d_in[1];
    float* out = (float*)d_out;

    norms_kernel<<<(2 * NN * 32) / 256, 256>>>(x, y);
    dim3 gD(NN / 64, NN / 64);
    dim3 bD(16, 16);
    dmat_kernel<<<gD, bD>>>(x, y);
    init_kernel<<<1, NBLK>>>();
    dp_kernel<<<NBLK, 32>>>(out);
}

// round 7
// speedup vs baseline: 2.6204x; 2.6204x over previous
#include <cuda_runtime.h>

#define NN 4096
#define DIM 64
#define INF_V 1e10f
#define NBLK 32           // 32 bands x 128 rows (one warp per band, 4 rows/lane)
#define WPB 16            // warps (bands) per block
#define NTILE 1024        // tile-columns (4 cols each)

// Scratch (static __device__ arrays: allocation-free per harness rules)
__device__ float g_D[(size_t)NN * NN];    // 64 MB cost matrix
__device__ float g_xn[NN];
__device__ float g_yn[NN];
__device__ float g_bnd[NBLK][NN];         // bottom boundary row of each band
__device__ int   g_prog[NBLK];            // tiles published per band

// ---------------- norms ----------------
__global__ void norms_kernel(const float* __restrict__ x, const float* __restrict__ y) {
    int w = (blockIdx.x * blockDim.x + threadIdx.x) >> 5;
    int lane = threadIdx.x & 31;
    if (w >= 2 * NN) return;
    const float* src = (w < NN) ? x : y;
    int row = (w < NN) ? w : w - NN;
    float a = src[row * DIM + lane];
    float b = src[row * DIM + 32 + lane];
    float s = a * a + b * b;
    #pragma unroll
    for (int o = 16; o; o >>= 1) s += __shfl_xor_sync(0xffffffffu, s, o);
    if (lane == 0) { if (w < NN) g_xn[row] = s; else g_yn[row] = s; }
}

// ---------------- D = |x|^2 + |y|^2 - 2 x.y  (64x64 tile per block) ----------------
__global__ void dmat_kernel(const float* __restrict__ x, const float* __restrict__ y) {
    __shared__ float xs[64][65];
    __shared__ float ys[64][65];
    int tx = threadIdx.x, ty = threadIdx.y;
    int tid = ty * 16 + tx;
    int rb = blockIdx.y * 64, cb = blockIdx.x * 64;

    for (int i = tid; i < 64 * 64; i += 256) {
        int rr = i >> 6, kk = i & 63;
        xs[rr][kk] = x[(rb + rr) * DIM + kk];
        ys[rr][kk] = y[(cb + rr) * DIM + kk];
    }
    __syncthreads();

    float acc[4][4] = {};
    #pragma unroll
    for (int k = 0; k < 64; k++) {
        float xv[4], yv[4];
        #pragma unroll
        for (int i = 0; i < 4; i++) xv[i] = xs[ty + 16 * i][k];
        #pragma unroll
        for (int j = 0; j < 4; j++) yv[j] = ys[tx + 16 * j][k];
        #pragma unroll
        for (int i = 0; i < 4; i++)
            #pragma unroll
            for (int j = 0; j < 4; j++)
                acc[i][j] += xv[i] * yv[j];
    }

    #pragma unroll
    for (int i = 0; i < 4; i++) {
        int r = rb + ty + 16 * i;
        float xnr = g_xn[r];
        #pragma unroll
        for (int j = 0; j < 4; j++) {
            int c = cb + tx + 16 * j;
            g_D[(size_t)r * NN + c] = xnr + g_yn[c] - 2.0f * acc[i][j];
        }
    }
}

// ---------------- reset progress flags ----------------
__global__ void init_kernel() {
    if (threadIdx.x < NBLK) g_prog[threadIdx.x] = 0;
}

// ---------------- DP wavefront: 4x4 register tiles, 16 bands per block ----------
__device__ __forceinline__ int ld_acq(const int* p) {
    int v;
    asm volatile("ld.acquire.gpu.u32 %0, [%1];" : "=r"(v) : "l"(p) : "memory");
    return v;
}
__device__ __forceinline__ void st_rel(int* p, int v) {
    asm volatile("st.release.gpu.u32 [%0], %1;" :: "l"(p), "r"(v) : "memory");
}

#define CELL(nv, u, d, l, cost) do {                                   \
    float m_ = fminf(fminf((u), (d)), (l));                            \
    float s_ = __expf(m_ - (u)) + __expf(m_ - (d)) + __expf(m_ - (l)); \
    (nv) = (cost) + m_ - __logf(s_);                                   \
} while (0)

__global__ void __launch_bounds__(32 * WPB, 1) dp_kernel(float* __restrict__ out) {
    __shared__ float topb[WPB][18];   // per-warp boundary window

    const int wid = threadIdx.x >> 5;
    const int L = threadIdx.x & 31;
    const int b = blockIdx.x * WPB + wid;        // band id (pipeline order)
    const int row0 = b * 128 + 4 * L;
    const float4* __restrict__ Dr0 = (const float4*)(g_D + (size_t)(row0 + 0) * NN);
    const float4* __restrict__ Dr1 = (const float4*)(g_D + (size_t)(row0 + 1) * NN);
    const float4* __restrict__ Dr2 = (const float4*)(g_D + (size_t)(row0 + 2) * NN);
    const float4* __restrict__ Dr3 = (const float4*)(g_D + (size_t)(row0 + 3) * NN);
    float* mybnd = g_bnd[b];
    const float* upbnd = (b > 0) ? g_bnd[b - 1] : (const float*)0;
    float* tb = topb[wid];

    float lft[4] = {INF_V, INF_V, INF_V, INF_V};  // v[row i][4j-1]
    float bot0 = INF_V, bot1 = INF_V, bot2 = INF_V, bot3 = INF_V; // row3 of last tile
    float dgv = INF_V;                            // v[row0-1][4j-1]

    // prefetch tile 0 costs
    float4 c0 = __ldg(Dr0), c1 = __ldg(Dr1), c2 = __ldg(Dr2), c3 = __ldg(Dr3);

    const int TT = NTILE + 31;
    #pragma unroll 1
    for (int tau = 0; tau < TT; tau++) {
        const int j = tau - L;                    // this lane's tile-column

        // ---- stage boundary window every 4 tiles (lane 0's consumption) ----
        if (b > 0 && tau < NTILE && (tau & 3) == 0) {
            if (L == 0) { while (ld_acq(&g_prog[b - 1]) < tau + 4) { } }
            __syncwarp();
            if (L < 17) {
                int col = 4 * tau - 1 + L;
                tb[L] = (col >= 0) ? __ldcg(&upbnd[col]) : INF_V;
            }
            __syncwarp();
        }

        // ---- prefetch next tile's costs (consumed next iteration) ----
        int jn = j + 1; if (jn < 0) jn = 0; if (jn > NTILE - 1) jn = NTILE - 1;
        float4 p0 = __ldg(Dr0 + jn);
        float4 p1 = __ldg(Dr1 + jn);
        float4 p2 = __ldg(Dr2 + jn);
        float4 p3 = __ldg(Dr3 + jn);

        // ---- top handoff: neighbor's bottom row from previous step ----
        float t0 = __shfl_up_sync(0xffffffffu, bot0, 1);
        float t1 = __shfl_up_sync(0xffffffffu, bot1, 1);
        float t2 = __shfl_up_sync(0xffffffffu, bot2, 1);
        float t3 = __shfl_up_sync(0xffffffffu, bot3, 1);
        if (L == 0) {
            if (b == 0) {
                t0 = t1 = t2 = t3 = INF_V;
                dgv = (tau == 0) ? 0.0f : INF_V;
            } else {
                int p = (tau & 3) * 4;
                dgv = tb[p];
                t0 = tb[p + 1]; t1 = tb[p + 2];
                t2 = tb[p + 3]; t3 = tb[p + 4];
            }
        }
        if (j == 0 && L > 0) dgv = INF_V;         // diag of col 0 is dp[.][-1]

        if (j >= 0 && j < NTILE) {
            float u0 = t0, u1 = t1, u2 = t2, u3 = t3;
            float nl[4];
            {   // row 0
                float d = dgv, l = lft[0], n0, n1, n2, n3;
                CELL(n0, u0, d, l, c0.x); d = u0; l = n0;
                CELL(n1, u1, d, l, c0.y); d = u1; l = n1;
                CELL(n2, u2, d, l, c0.z); d = u2; l = n2;
                CELL(n3, u3, d, l, c0.w);
                nl[0] = n3; u0 = n0; u1 = n1; u2 = n2; u3 = n3;
            }
            {   // row 1 (diag at k=0 is OLD lft[0])
                float d = lft[0], l = lft[1], n0, n1, n2, n3;
                CELL(n0, u0, d, l, c1.x); d = u0; l = n0;
                CELL(n1, u1, d, l, c1.y); d = u1; l = n1;
                CELL(n2, u2, d, l, c1.z); d = u2; l = n2;
                CELL(n3, u3, d, l, c1.w);
                nl[1] = n3; u0 = n0; u1 = n1; u2 = n2; u3 = n3;
            }
            {   // row 2
                float d = lft[1], l = lft[2], n0, n1, n2, n3;
                CELL(n0, u0, d, l, c2.x); d = u0; l = n0;
                CELL(n1, u1, d, l, c2.y); d = u1; l = n1;
                CELL(n2, u2, d, l, c2.z); d = u2; l = n2;
                CELL(n3, u3, d, l, c2.w);
                nl[2] = n3; u0 = n0; u1 = n1; u2 = n2; u3 = n3;
            }
            {   // row 3
                float d = lft[2], l = lft[3], n0, n1, n2, n3;
                CELL(n0, u0, d, l, c3.x); d = u0; l = n0;
                CELL(n1, u1, d, l, c3.y); d = u1; l = n1;
                CELL(n2, u2, d, l, c3.z); d = u2; l = n2;
                CELL(n3, u3, d, l, c3.w);
                nl[3] = n3; u0 = n0; u1 = n1; u2 = n2; u3 = n3;
            }
            lft[0] = nl[0]; lft[1] = nl[1]; lft[2] = nl[2]; lft[3] = nl[3];
            bot0 = u0; bot1 = u1; bot2 = u2; bot3 = u3;

            if (L == 31) {
                *(float4*)&mybnd[4 * j] = make_float4(bot0, bot1, bot2, bot3);
                if ((j & 3) == 3 && b < NBLK - 1)
                    st_rel(&g_prog[b], j + 1);   // release orders mybnd stores
            }
        }
        dgv = t3;                                 // diag for next tile = top[3]

        c0 = p0; c1 = p1; c2 = p2; c3 = p3;       // rotate cost buffers
    }

    if (b == NBLK - 1 && L == 31) out[0] = lft[3];   // dp[4096][4096]
}

extern "C" void kernel_launch(void* const* d_in, const int* in_sizes, int n_in,
                              void* d_out, int out_size) {
    const float* x = (const float*)d_in[0];
    const float* y = (const float*)d_in[1];
    float* out = (float*)d_out;

    norms_kernel<<<(2 * NN * 32) / 256, 256>>>(x, y);
    dim3 gD(NN / 64, NN / 64);
    dim3 bD(16, 16);
    dmat_kernel<<<gD, bD>>>(x, y);
    init_kernel<<<1, NBLK>>>();
    dp_kernel<<<NBLK / WPB, 32 * WPB>>>(out);
}

// round 8
// speedup vs baseline: 3.1253x; 1.1927x over previous
#include <cuda_runtime.h>

#define NN 4096
#define DIM 64
#define INF_V 1e10f
#define NBLK 64           // 64 bands x 64 rows (one warp per band, 2 rows/lane)
#define WPB 8             // warps (bands) per block -> 2 warps per SMSP
#define NTILE 1024        // tile-columns (4 cols each)
#define LOG2E 1.4426950408889634f
#define LN2   0.6931471805599453f

// Scratch (static __device__ arrays: allocation-free per harness rules)
__device__ float g_D[(size_t)NN * NN];    // cost matrix, PRE-SCALED by log2(e)
__device__ float g_xn[NN];
__device__ float g_yn[NN];
__device__ float g_bnd[NBLK][NN];         // bottom boundary row of each band (base-2 units)
__device__ int   g_prog[NBLK];            // tiles published per band

// ---------------- norms ----------------
__global__ void norms_kernel(const float* __restrict__ x, const float* __restrict__ y) {
    int w = (blockIdx.x * blockDim.x + threadIdx.x) >> 5;
    int lane = threadIdx.x & 31;
    if (w >= 2 * NN) return;
    const float* src = (w < NN) ? x : y;
    int row = (w < NN) ? w : w - NN;
    float a = src[row * DIM + lane];
    float b = src[row * DIM + 32 + lane];
    float s = a * a + b * b;
    #pragma unroll
    for (int o = 16; o; o >>= 1) s += __shfl_xor_sync(0xffffffffu, s, o);
    if (lane == 0) { if (w < NN) g_xn[row] = s; else g_yn[row] = s; }
}

// ---------------- D2 = (|x|^2 + |y|^2 - 2 x.y) * log2(e) ----------------
__global__ void dmat_kernel(const float* __restrict__ x, const float* __restrict__ y) {
    __shared__ float xs[64][65];
    __shared__ float ys[64][65];
    int tx = threadIdx.x, ty = threadIdx.y;
    int tid = ty * 16 + tx;
    int rb = blockIdx.y * 64, cb = blockIdx.x * 64;

    for (int i = tid; i < 64 * 64; i += 256) {
        int rr = i >> 6, kk = i & 63;
        xs[rr][kk] = x[(rb + rr) * DIM + kk];
        ys[rr][kk] = y[(cb + rr) * DIM + kk];
    }
    __syncthreads();

    float acc[4][4] = {};
    #pragma unroll
    for (int k = 0; k < 64; k++) {
        float xv[4], yv[4];
        #pragma unroll
        for (int i = 0; i < 4; i++) xv[i] = xs[ty + 16 * i][k];
        #pragma unroll
        for (int j = 0; j < 4; j++) yv[j] = ys[tx + 16 * j][k];
        #pragma unroll
        for (int i = 0; i < 4; i++)
            #pragma unroll
            for (int j = 0; j < 4; j++)
                acc[i][j] += xv[i] * yv[j];
    }

    #pragma unroll
    for (int i = 0; i < 4; i++) {
        int r = rb + ty + 16 * i;
        float xnr = g_xn[r];
        #pragma unroll
        for (int j = 0; j < 4; j++) {
            int c = cb + tx + 16 * j;
            g_D[(size_t)r * NN + c] = (xnr + g_yn[c] - 2.0f * acc[i][j]) * LOG2E;
        }
    }
}

// ---------------- reset progress flags ----------------
__global__ void init_kernel() {
    if (threadIdx.x < NBLK) g_prog[threadIdx.x] = 0;
}

// ---------------- DP wavefront: 2x4 tiles, 8 bands/block, 2 warps/SMSP ------
__device__ __forceinline__ int ld_acq(const int* p) {
    int v;
    asm volatile("ld.acquire.gpu.u32 %0, [%1];" : "=r"(v) : "l"(p) : "memory");
    return v;
}
__device__ __forceinline__ void st_rel(int* p, int v) {
    asm volatile("st.release.gpu.u32 [%0], %1;" :: "l"(p), "r"(v) : "memory");
}
__device__ __forceinline__ float ex2(float x) {
    float r; asm("ex2.approx.f32 %0, %1;" : "=f"(r) : "f"(x)); return r;
}
__device__ __forceinline__ float lg2(float x) {
    float r; asm("lg2.approx.f32 %0, %1;" : "=f"(r) : "f"(x)); return r;
}

// base-2 softmin cell, 3 MUFU: one exp term is exactly 1 (the min).
// mid/max by exact min-max selection (no cancellation).
#define CELL(nv, u, d, l, cost) do {                                   \
    float p_ = fminf((u), (d));                                        \
    float q_ = fmaxf((u), (d));                                        \
    float m_ = fminf(p_, (l));                                         \
    float md_ = fmaxf(p_, fminf(q_, (l)));                             \
    float mx_ = fmaxf(q_, (l));                                        \
    float s_ = 1.0f + ex2(m_ - md_) + ex2(m_ - mx_);                   \
    (nv) = (cost) + m_ - lg2(s_);                                      \
} while (0)

__global__ void __launch_bounds__(32 * WPB, 1) dp_kernel(float* __restrict__ out) {
    __shared__ float topb[WPB][18];   // per-warp boundary window

    const int wid = threadIdx.x >> 5;
    const int L = threadIdx.x & 31;
    const int b = blockIdx.x * WPB + wid;        // band id (pipeline order)
    const int row0 = b * 64 + 2 * L;
    const float4* __restrict__ Dr0 = (const float4*)(g_D + (size_t)(row0 + 0) * NN);
    const float4* __restrict__ Dr1 = (const float4*)(g_D + (size_t)(row0 + 1) * NN);
    float* mybnd = g_bnd[b];
    const float* upbnd = (b > 0) ? g_bnd[b - 1] : (const float*)0;
    float* tb = topb[wid];

    float lft0 = INF_V, lft1 = INF_V;   // v[row0][4j-1], v[row1][4j-1]
    float bot0 = INF_V, bot1 = INF_V, bot2 = INF_V, bot3 = INF_V; // row1, last tile
    float dgv = INF_V;                  // v[row0-1][4j-1]

    // prefetch tile 0 costs
    float4 c0 = __ldg(Dr0), c1 = __ldg(Dr1);

    const int TT = NTILE + 31;
    #pragma unroll 1
    for (int tau = 0; tau < TT; tau++) {
        const int j = tau - L;                    // this lane's tile-column

        // ---- stage boundary window every 4 tiles (R4 protocol, verbatim) ----
        if (b > 0 && tau < NTILE && (tau & 3) == 0) {
            if (L == 0) { while (ld_acq(&g_prog[b - 1]) < tau + 4) { } }
            __syncwarp();
            if (L < 17) {
                int col = 4 * tau - 1 + L;
                tb[L] = (col >= 0) ? __ldcg(&upbnd[col]) : INF_V;
            }
            __syncwarp();
        }

        // ---- prefetch next tile's costs ----
        int jn = j + 1; if (jn < 0) jn = 0; if (jn > NTILE - 1) jn = NTILE - 1;
        float4 p0 = __ldg(Dr0 + jn);
        float4 p1 = __ldg(Dr1 + jn);

        // ---- top handoff: neighbor's bottom row from previous step ----
        float t0 = __shfl_up_sync(0xffffffffu, bot0, 1);
        float t1 = __shfl_up_sync(0xffffffffu, bot1, 1);
        float t2 = __shfl_up_sync(0xffffffffu, bot2, 1);
        float t3 = __shfl_up_sync(0xffffffffu, bot3, 1);
        if (L == 0) {
            if (b == 0) {
                t0 = t1 = t2 = t3 = INF_V;
                dgv = (tau == 0) ? 0.0f : INF_V;
            } else {
                int p = (tau & 3) * 4;
                dgv = tb[p];
                t0 = tb[p + 1]; t1 = tb[p + 2];
                t2 = tb[p + 3]; t3 = tb[p + 4];
            }
        }
        if (j == 0 && L > 0) dgv = INF_V;         // diag of col 0 is dp[.][-1]

        if (j >= 0 && j < NTILE) {
            float u0 = t0, u1 = t1, u2 = t2, u3 = t3;
            float n0, n1, n2, n3, newl0;
            {   // row 0
                float d = dgv, l = lft0;
                CELL(n0, u0, d, l, c0.x); d = u0; l = n0;
                CELL(n1, u1, d, l, c0.y); d = u1; l = n1;
                CELL(n2, u2, d, l, c0.z); d = u2; l = n2;
                CELL(n3, u3, d, l, c0.w);
                newl0 = n3;
                u0 = n0; u1 = n1; u2 = n2; u3 = n3;
            }
            {   // row 1 (diag at k=0 is OLD lft0)
                float d = lft0, l = lft1;
                CELL(n0, u0, d, l, c1.x); d = u0; l = n0;
                CELL(n1, u1, d, l, c1.y); d = u1; l = n1;
                CELL(n2, u2, d, l, c1.z); d = u2; l = n2;
                CELL(n3, u3, d, l, c1.w);
                u0 = n0; u1 = n1; u2 = n2; u3 = n3;
            }
            lft0 = newl0; lft1 = u3;
            bot0 = u0; bot1 = u1; bot2 = u2; bot3 = u3;

            if (L == 31) {
                *(float4*)&mybnd[4 * j] = make_float4(bot0, bot1, bot2, bot3);
                if ((j & 3) == 3 && b < NBLK - 1)
                    st_rel(&g_prog[b], j + 1);   // release orders mybnd stores
            }
        }
        dgv = t3;                                 // diag for next tile = top[3]
        c0 = p0; c1 = p1;                         // rotate cost buffers
    }

    if (b == NBLK - 1 && L == 31) out[0] = lft1 * LN2;   // dp[4096][4096]
}

extern "C" void kernel_launch(void* const* d_in, const int* in_sizes, int n_in,
                              void* d_out, int out_size) {
    const float* x = (const float*)d_in[0];
    const float* y = (const float*)d_in[1];
    float* out = (float*)d_out;

    norms_kernel<<<(2 * NN * 32) / 256, 256>>>(x, y);
    dim3 gD(NN / 64, NN / 64);
    dim3 bD(16, 16);
    dmat_kernel<<<gD, bD>>>(x, y);
    init_kernel<<<1, NBLK>>>();
    dp_kernel<<<NBLK / WPB, 32 * WPB>>>(out);
}

// round 9
// speedup vs baseline: 4.2102x; 1.3471x over previous
#include <cuda_runtime.h>

#define NN 4096
#define DIM 64
#define INF_V 1e10f
#define NBLK 32           // 32 bands x 128 rows (one warp per band, 4 rows/lane)
#define NTILE 1024        // tile-columns (4 cols each)
#define LOG2E 1.4426950408889634f
#define LN2   0.6931471805599453f

// Scratch (static __device__ arrays: allocation-free per harness rules)
__device__ float g_D[(size_t)NN * NN];    // cost matrix, PRE-SCALED by log2(e)
__device__ float g_xn[NN];
__device__ float g_yn[NN];
__device__ float g_bnd[NBLK][NN];         // bottom boundary row of each band (base-2)
__device__ int   g_prog[NBLK];            // tiles published per band

// ---------------- norms ----------------
__global__ void norms_kernel(const float* __restrict__ x, const float* __restrict__ y) {
    int w = (blockIdx.x * blockDim.x + threadIdx.x) >> 5;
    int lane = threadIdx.x & 31;
    if (w >= 2 * NN) return;
    const float* src = (w < NN) ? x : y;
    int row = (w < NN) ? w : w - NN;
    float a = src[row * DIM + lane];
    float b = src[row * DIM + 32 + lane];
    float s = a * a + b * b;
    #pragma unroll
    for (int o = 16; o; o >>= 1) s += __shfl_xor_sync(0xffffffffu, s, o);
    if (lane == 0) { if (w < NN) g_xn[row] = s; else g_yn[row] = s; }
}

// ---------------- D2 = (|x|^2 + |y|^2 - 2 x.y) * log2(e) ----------------
__global__ void dmat_kernel(const float* __restrict__ x, const float* __restrict__ y) {
    __shared__ float xs[64][65];
    __shared__ float ys[64][65];
    int tx = threadIdx.x, ty = threadIdx.y;
    int tid = ty * 16 + tx;
    int rb = blockIdx.y * 64, cb = blockIdx.x * 64;

    for (int i = tid; i < 64 * 64; i += 256) {
        int rr = i >> 6, kk = i & 63;
        xs[rr][kk] = x[(rb + rr) * DIM + kk];
        ys[rr][kk] = y[(cb + rr) * DIM + kk];
    }
    __syncthreads();

    float acc[4][4] = {};
    #pragma unroll
    for (int k = 0; k < 64; k++) {
        float xv[4], yv[4];
        #pragma unroll
        for (int i = 0; i < 4; i++) xv[i] = xs[ty + 16 * i][k];
        #pragma unroll
        for (int j = 0; j < 4; j++) yv[j] = ys[tx + 16 * j][k];
        #pragma unroll
        for (int i = 0; i < 4; i++)
            #pragma unroll
            for (int j = 0; j < 4; j++)
                acc[i][j] += xv[i] * yv[j];
    }

    #pragma unroll
    for (int i = 0; i < 4; i++) {
        int r = rb + ty + 16 * i;
        float xnr = g_xn[r];
        #pragma unroll
        for (int j = 0; j < 4; j++) {
            int c = cb + tx + 16 * j;
            g_D[(size_t)r * NN + c] = (xnr + g_yn[c] - 2.0f * acc[i][j]) * LOG2E;
        }
    }
}

// ---------------- reset progress flags ----------------
__global__ void init_kernel() {
    if (threadIdx.x < NBLK) g_prog[threadIdx.x] = 0;
}

// ---------------- DP wavefront: 4x4 tiles in wavefront issue order ----------
__device__ __forceinline__ int ld_acq(const int* p) {
    int v;
    asm volatile("ld.acquire.gpu.u32 %0, [%1];" : "=r"(v) : "l"(p) : "memory");
    return v;
}
__device__ __forceinline__ void st_rel(int* p, int v) {
    asm volatile("st.release.gpu.u32 [%0], %1;" :: "l"(p), "r"(v) : "memory");
}
__device__ __forceinline__ float ex2(float x) {
    float r; asm("ex2.approx.f32 %0, %1;" : "=f"(r) : "f"(x)); return r;
}
__device__ __forceinline__ float lg2(float x) {
    float r; asm("lg2.approx.f32 %0, %1;" : "=f"(r) : "f"(x)); return r;
}

// base-2 softmin cell, 3 MUFU: the min's exp term is exactly 1.
#define CELL(nv, u, d, l, cost) do {                                   \
    float p_ = fminf((u), (d));                                        \
    float q_ = fmaxf((u), (d));                                        \
    float m_ = fminf(p_, (l));                                         \
    float md_ = fmaxf(p_, fminf(q_, (l)));                             \
    float mx_ = fmaxf(q_, (l));                                        \
    float s_ = 1.0f + ex2(m_ - md_) + ex2(m_ - mx_);                   \
    (nv) = (cost) + m_ - lg2(s_);                                      \
} while (0)

__global__ void __launch_bounds__(32, 1) dp_kernel(float* __restrict__ out) {
    __shared__ float topb[18];   // boundary window: cols [4*tau-1 .. 4*tau+15]

    const int b = blockIdx.x;
    const int L = threadIdx.x;
    const int row0 = b * 128 + 4 * L;
    const float4* __restrict__ Dr0 = (const float4*)(g_D + (size_t)(row0 + 0) * NN);
    const float4* __restrict__ Dr1 = (const float4*)(g_D + (size_t)(row0 + 1) * NN);
    const float4* __restrict__ Dr2 = (const float4*)(g_D + (size_t)(row0 + 2) * NN);
    const float4* __restrict__ Dr3 = (const float4*)(g_D + (size_t)(row0 + 3) * NN);
    float* mybnd = g_bnd[b];
    const float* upbnd = (b > 0) ? g_bnd[b - 1] : (const float*)0;

    float lft0 = INF_V, lft1 = INF_V, lft2 = INF_V, lft3 = INF_V; // right edge of prev tile
    float bot0 = INF_V, bot1 = INF_V, bot2 = INF_V, bot3 = INF_V; // bottom row of prev tile
    float dgv = INF_V;                                             // v[row0-1][4j-1]

    float4 c0 = __ldg(Dr0), c1 = __ldg(Dr1), c2 = __ldg(Dr2), c3 = __ldg(Dr3);

    const int TT = NTILE + 31;
    #pragma unroll 1
    for (int tau = 0; tau < TT; tau++) {
        const int j = tau - L;                    // this lane's tile-column

        // ---- stage boundary window every 4 tiles (R4 protocol, verbatim) ----
        if (b > 0 && tau < NTILE && (tau & 3) == 0) {
            if (L == 0) { while (ld_acq(&g_prog[b - 1]) < tau + 4) { } }
            __syncwarp();
            if (L < 17) {
                int col = 4 * tau - 1 + L;
                topb[L] = (col >= 0) ? __ldcg(&upbnd[col]) : INF_V;
            }
            __syncwarp();
        }

        // ---- prefetch next tile's costs ----
        int jn = j + 1; if (jn < 0) jn = 0; if (jn > NTILE - 1) jn = NTILE - 1;
        float4 p0 = __ldg(Dr0 + jn);
        float4 p1 = __ldg(Dr1 + jn);
        float4 p2 = __ldg(Dr2 + jn);
        float4 p3 = __ldg(Dr3 + jn);

        // ---- top handoff: neighbor's bottom row from previous step ----
        float t0 = __shfl_up_sync(0xffffffffu, bot0, 1);
        float t1 = __shfl_up_sync(0xffffffffu, bot1, 1);
        float t2 = __shfl_up_sync(0xffffffffu, bot2, 1);
        float t3 = __shfl_up_sync(0xffffffffu, bot3, 1);
        if (L == 0) {
            if (b == 0) {
                t0 = t1 = t2 = t3 = INF_V;
                dgv = (tau == 0) ? 0.0f : INF_V;
            } else {
                int p = (tau & 3) * 4;
                dgv = topb[p];
                t0 = topb[p + 1]; t1 = topb[p + 2];
                t2 = topb[p + 3]; t3 = topb[p + 4];
            }
        }
        if (j == 0 && L > 0) dgv = INF_V;         // diag of col 0 is dp[.][-1]

        if (j >= 0 && j < NTILE) {
            // 4x4 tile, cells emitted in anti-diagonal (wavefront) order so the
            // in-order scheduler overlaps independent cells of each rank.
            // V[i][k]: row i (global row0+i), col k (global 4j+k).
            float V00, V01, V02, V03;
            float V10, V11, V12, V13;
            float V20, V21, V22, V23;
            float V30, V31, V32, V33;
            // rank 0
            CELL(V00, t0,  dgv,  lft0, c0.x);
            // rank 1
            CELL(V01, t1,  t0,   V00,  c0.y);
            CELL(V10, V00, lft0, lft1, c1.x);
            // rank 2
            CELL(V02, t2,  t1,   V01,  c0.z);
            CELL(V11, V01, V00,  V10,  c1.y);
            CELL(V20, V10, lft1, lft2, c2.x);
            // rank 3
            CELL(V03, t3,  t2,   V02,  c0.w);
            CELL(V12, V02, V01,  V11,  c1.z);
            CELL(V21, V11, V10,  V20,  c2.y);
            CELL(V30, V20, lft2, lft3, c3.x);
            // rank 4
            CELL(V13, V03, V02,  V12,  c1.w);
            CELL(V22, V12, V11,  V21,  c2.z);
            CELL(V31, V21, V20,  V30,  c3.y);
            // rank 5
            CELL(V23, V13, V12,  V22,  c2.w);
            CELL(V32, V22, V21,  V31,  c3.z);
            // rank 6
            CELL(V33, V23, V22,  V32,  c3.w);

            lft0 = V03; lft1 = V13; lft2 = V23; lft3 = V33;
            bot0 = V30; bot1 = V31; bot2 = V32; bot3 = V33;

            if (L == 31) {
                *(float4*)&mybnd[4 * j] = make_float4(bot0, bot1, bot2, bot3);
                if ((j & 3) == 3 && b < NBLK - 1)
                    st_rel(&g_prog[b], j + 1);   // release orders mybnd stores
            }
        }
        dgv = t3;                                 // diag for next tile = top[3]

        c0 = p0; c1 = p1; c2 = p2; c3 = p3;       // rotate cost buffers
    }

    if (b == NBLK - 1 && L == 31) out[0] = lft3 * LN2;   // dp[4096][4096]
}

extern "C" void kernel_launch(void* const* d_in, const int* in_sizes, int n_in,
                              void* d_out, int out_size) {
    const float* x = (const float*)d_in[0];
    const float* y = (const float*)d_in[1];
    float* out = (float*)d_out;

    norms_kernel<<<(2 * NN * 32) / 256, 256>>>(x, y);
    dim3 gD(NN / 64, NN / 64);
    dim3 bD(16, 16);
    dmat_kernel<<<gD, bD>>>(x, y);
    init_kernel<<<1, NBLK>>>();
    dp_kernel<<<NBLK, 32>>>(out);
}